// round 6
// baseline (speedup 1.0000x reference)
#include <cuda_runtime.h>

// 3-layer LSTM (IN=5, H=50) + FC(50->1), B=1024, T=512.
// v5 = R3 architecture (400 gate threads = 12.5 warps) with the spill fixed:
// no register array is ever indexed by a runtime value.
// Thread (j, ks, bg): accumulates gate rows {j, j+50, j+100, j+150} over
// K-half ks for batches {2bg, 2bg+1} (8 packed f32x2 accs = 16 regs);
// one shfl.bfly(4) combines K halves; thread updates batch 2bg+ks fully in
// registers (cell state never leaves registers).
// W2/W3 padded with a zero kq-block so both ks lanes run exactly 13 unrolled
// iterations (no divergence). Biases live in registers. 3 barriers/step.

#define T_STEPS   512
#define IN_DIM    5
#define HID       50
#define NB        7
#define NTHREADS  448
#define GRID      148
#define WSTR      816     // 200 rows * 4 + 16 pad; ks-stride == 64B mod 128B

// smem offsets (floats)
enum {
    W1_OFF = 0,                 // 14 * 816 = 11424
    W2_OFF = 11424,             // 26 * 816 = 21216 (kq=25 block zeroed)
    W3_OFF = 32640,             // 21216
    V1_OFF = 53856,             // 2 bufs * 7 * 60   [x(5),pad,h1(50)]
    V2_OFF = 54696,             // 2 bufs * 7 * 108  [h1,h2,pad8]
    V3_OFF = 56208,             // 2 bufs * 7 * 108  [h2,h3,pad8]
    SH_FLOATS = 57720           // 230880 bytes
};
#define V1S 60
#define V2S 108
#define V1B (NB * V1S)          // 420 per parity buffer
#define V2B (NB * V2S)          // 756

typedef unsigned long long ull;

__device__ __forceinline__ ull ffma2(ull a, ull b, ull c) {
    ull d;
    asm("fma.rn.f32x2 %0, %1, %2, %3;" : "=l"(d) : "l"(a), "l"(b), "l"(c));
    return d;
}
__device__ __forceinline__ float fast_ex2(float x) {
    float y; asm("ex2.approx.ftz.f32 %0, %1;" : "=f"(y) : "f"(x)); return y;
}
__device__ __forceinline__ float fast_rcp(float x) {
    float y; asm("rcp.approx.ftz.f32 %0, %1;" : "=f"(y) : "f"(x)); return y;
}
__device__ __forceinline__ float sigm(float x) {
    return fast_rcp(1.0f + fast_ex2(-1.4426950408889634f * x));
}
__device__ __forceinline__ float tanh_acc(float x) {
    float r = fast_rcp(1.0f + fast_ex2(-2.8853900817779268f * x));
    return r + r - 1.0f;
}
__device__ __forceinline__ float lohi(ull a) {
    float lo, hi;
    asm("mov.b64 {%0, %1}, %2;" : "=f"(lo), "=f"(hi) : "l"(a));
    return lo + hi;
}

// Accumulate 4 gate rows over NITER kq blocks (kq = ks + 2*i) for the two
// batch slots. All register indices compile-time constant.
template<int NITER>
__device__ __forceinline__ void gate_accum(const float* __restrict__ shw,
                                           const float* __restrict__ v0,
                                           const float* __restrict__ v1,
                                           int j, int ks, ull acc[4][2]) {
#pragma unroll
    for (int g = 0; g < 4; g++) { acc[g][0] = 0ull; acc[g][1] = 0ull; }
#pragma unroll
    for (int i = 0; i < NITER; i++) {
        const int koff = 2 * i;   // + ks at runtime
        const ulonglong2* wq = reinterpret_cast<const ulonglong2*>(
            shw + (ks + koff) * WSTR);
        ulonglong2 w0 = wq[j];
        ulonglong2 w1 = wq[j + HID];
        ulonglong2 w2 = wq[j + 2 * HID];
        ulonglong2 w3 = wq[j + 3 * HID];
        ulonglong2 va = *reinterpret_cast<const ulonglong2*>(v0 + (ks + koff) * 4);
        ulonglong2 vb = *reinterpret_cast<const ulonglong2*>(v1 + (ks + koff) * 4);
        acc[0][0] = ffma2(w0.x, va.x, acc[0][0]);
        acc[0][0] = ffma2(w0.y, va.y, acc[0][0]);
        acc[1][0] = ffma2(w1.x, va.x, acc[1][0]);
        acc[1][0] = ffma2(w1.y, va.y, acc[1][0]);
        acc[2][0] = ffma2(w2.x, va.x, acc[2][0]);
        acc[2][0] = ffma2(w2.y, va.y, acc[2][0]);
        acc[3][0] = ffma2(w3.x, va.x, acc[3][0]);
        acc[3][0] = ffma2(w3.y, va.y, acc[3][0]);
        acc[0][1] = ffma2(w0.x, vb.x, acc[0][1]);
        acc[0][1] = ffma2(w0.y, vb.y, acc[0][1]);
        acc[1][1] = ffma2(w1.x, vb.x, acc[1][1]);
        acc[1][1] = ffma2(w1.y, vb.y, acc[1][1]);
        acc[2][1] = ffma2(w2.x, vb.x, acc[2][1]);
        acc[2][1] = ffma2(w2.y, vb.y, acc[2][1]);
        acc[3][1] = ffma2(w3.x, vb.x, acc[3][1]);
        acc[3][1] = ffma2(w3.y, vb.y, acc[3][1]);
    }
}

// Combine K halves across ks partner (lane xor 4) using only constant
// register indices (SEL, not dynamic indexing), then c/h update.
__device__ __forceinline__ void reduce_update(const ull acc[4][2], int ks,
                                              unsigned mask, const float* bz,
                                              bool dov, float& c,
                                              float* sh, int d1, int d2,
                                              bool has2) {
    float tot[4];
#pragma unroll
    for (int g = 0; g < 4; g++) {
        float l0 = lohi(acc[g][0]);
        float l1 = lohi(acc[g][1]);
        float own = ks ? l1 : l0;     // my batch's partial (my K half)
        float oth = ks ? l0 : l1;     // partner batch's partial (my K half)
        float got = __shfl_xor_sync(mask, oth, 4);
        tot[g] = own + got + bz[g];
    }
    if (dov) {
        float iv = sigm(tot[0]);
        float fv = sigm(tot[1]);
        float gv = tanh_acc(tot[2]);
        float ov = sigm(tot[3]);
        c = fv * c + iv * gv;
        float h = ov * tanh_acc(c);
        sh[d1] = h;
        if (has2) sh[d2] = h;
    }
}

__global__ void __launch_bounds__(NTHREADS, 1)
lstm3_fused_kernel(const float* __restrict__ x,
                   const float* __restrict__ Wih1, const float* __restrict__ Whh1,
                   const float* __restrict__ bih1, const float* __restrict__ bhh1,
                   const float* __restrict__ Wih2, const float* __restrict__ Whh2,
                   const float* __restrict__ bih2, const float* __restrict__ bhh2,
                   const float* __restrict__ Wih3, const float* __restrict__ Whh3,
                   const float* __restrict__ bih3, const float* __restrict__ bhh3,
                   const float* __restrict__ fcW, const float* __restrict__ fcb,
                   float* __restrict__ out) {
    extern __shared__ float sh[];
    const int tid = threadIdx.x;
    const int bid = blockIdx.x;

    int b0, cnt;
    if (bid < 136) { b0 = bid * 7;               cnt = 7; }
    else           { b0 = 952 + (bid - 136) * 6; cnt = 6; }

    // zero v buffers and the W2/W3 pad blocks (kq = 25)
    for (int i = V1_OFF + tid; i < SH_FLOATS; i += NTHREADS) sh[i] = 0.0f;
    for (int i = tid; i < WSTR; i += NTHREADS) {
        sh[W2_OFF + 25 * WSTR + i] = 0.0f;
        sh[W3_OFF + 25 * WSTR + i] = 0.0f;
    }

    // stage weights: [kq][row][k&3], kq-stride WSTR
    for (int idx = tid; idx < 200 * 56; idx += NTHREADS) {
        int g = idx / 56, k = idx - g * 56;
        float v;
        if (k < IN_DIM)       v = Wih1[g * IN_DIM + k];
        else if (k == IN_DIM) v = 0.0f;
        else                  v = Whh1[g * HID + (k - 6)];
        sh[W1_OFF + (k >> 2) * WSTR + g * 4 + (k & 3)] = v;
    }
    for (int idx = tid; idx < 200 * 100; idx += NTHREADS) {
        int g = idx / 100, k = idx - g * 100;
        float v = (k < HID) ? Wih2[g * HID + k] : Whh2[g * HID + (k - HID)];
        sh[W2_OFF + (k >> 2) * WSTR + g * 4 + (k & 3)] = v;
    }
    for (int idx = tid; idx < 200 * 100; idx += NTHREADS) {
        int g = idx / 100, k = idx - g * 100;
        float v = (k < HID) ? Wih3[g * HID + k] : Whh3[g * HID + (k - HID)];
        sh[W3_OFF + (k >> 2) * WSTR + g * 4 + (k & 3)] = v;
    }
    // x(t=0) into v1 buf0
    if (tid < NB * IN_DIM) {
        int b = tid / IN_DIM, d = tid - b * IN_DIM;
        if (b < cnt)
            sh[V1_OFF + b * V1S + d] = x[(size_t)(b0 + b) * T_STEPS * IN_DIM + d];
    }

    const bool gate = (tid < 400);
    const int j  = tid >> 3;          // 0..49
    const int ks = (tid >> 2) & 1;    // 0..1 (lane bit 2)
    const int bg = tid & 3;           // 0..3
    const int bs0 = 2 * bg;
    const int bs1 = (2 * bg + 1 < NB) ? 2 * bg + 1 : NB - 1;  // clamp
    const int myb = 2 * bg + ks;
    const bool dov = gate && (myb < NB) && (myb < cnt);
    const unsigned mask = (tid < 384) ? 0xFFFFFFFFu : 0x0000FFFFu;

    // biases straight from global into registers (one-time)
    float bz1[4], bz2[4], bz3[4];
    if (gate) {
#pragma unroll
        for (int g = 0; g < 4; g++) {
            bz1[g] = bih1[g * HID + j] + bhh1[g * HID + j];
            bz2[g] = bih2[g * HID + j] + bhh2[g * HID + j];
            bz3[g] = bih3[g * HID + j] + bhh3[g * HID + j];
        }
    }
    float c1 = 0.f, c2 = 0.f, c3 = 0.f;

    // spare threads (400..447): x prefetch slots
    int pb = 0, pd = 0; bool pth = false;
    if (tid >= 400 && tid < 400 + NB * IN_DIM) {
        int i = tid - 400;
        pb = i / IN_DIM; pd = i - pb * IN_DIM;
        pth = (pb < cnt);
    }
    __syncthreads();

    for (int t = 0; t < T_STEPS; t++) {
        const int p = t & 1, q = p ^ 1;
        float xv = 0.0f;
        const bool pv = pth && (t + 1 < T_STEPS);

        // ---- layer 1: v1[p] = [x(t), h1(t-1)], KQ=14 -> 7 iters both ks ----
        if (gate) {
            ull acc[4][2];
            const float* vb = sh + V1_OFF + p * V1B;
            gate_accum<7>(sh + W1_OFF, vb + bs0 * V1S, vb + bs1 * V1S, j, ks, acc);
            reduce_update(acc, ks, mask, bz1, dov, c1, sh,
                          V1_OFF + q * V1B + myb * V1S + 6 + j,
                          V2_OFF + p * V2B + myb * V2S + j, true);
        } else if (pv) {
            xv = x[(size_t)(b0 + pb) * T_STEPS * IN_DIM + (t + 1) * IN_DIM + pd];
        }
        __syncthreads();

        // ---- layer 2: v2[p] = [h1(t), h2(t-1)], KQ=26 padded -> 13 iters ----
        if (gate) {
            ull acc[4][2];
            const float* vb = sh + V2_OFF + p * V2B;
            gate_accum<13>(sh + W2_OFF, vb + bs0 * V2S, vb + bs1 * V2S, j, ks, acc);
            reduce_update(acc, ks, mask, bz2, dov, c2, sh,
                          V2_OFF + q * V2B + myb * V2S + HID + j,
                          V3_OFF + p * V2B + myb * V2S + j, true);
        } else if (pv) {
            sh[V1_OFF + q * V1B + pb * V1S + pd] = xv;   // commit x(t+1)
        }
        __syncthreads();

        // ---- layer 3: v3[p] = [h2(t), h3(t-1)] ----
        if (gate) {
            ull acc[4][2];
            const float* vb = sh + V3_OFF + p * V2B;
            gate_accum<13>(sh + W3_OFF, vb + bs0 * V2S, vb + bs1 * V2S, j, ks, acc);
            reduce_update(acc, ks, mask, bz3, dov, c3, sh,
                          V3_OFF + q * V2B + myb * V2S + HID + j, 0, false);
        }
        __syncthreads();
    }

    // FC: t=511 wrote parity q=0 -> final h3 in v3 buf0
    if (tid < cnt) {
        float a = fcb[0];
#pragma unroll
        for (int jj = 0; jj < HID; jj++)
            a += fcW[jj] * sh[V3_OFF + tid * V2S + HID + jj];
        out[b0 + tid] = a;
    }
}

extern "C" void kernel_launch(void* const* d_in, const int* in_sizes, int n_in,
                              void* d_out, int out_size) {
    const float* x    = (const float*)d_in[0];
    const float* Wih1 = (const float*)d_in[1];
    const float* Whh1 = (const float*)d_in[2];
    const float* bih1 = (const float*)d_in[3];
    const float* bhh1 = (const float*)d_in[4];
    const float* Wih2 = (const float*)d_in[5];
    const float* Whh2 = (const float*)d_in[6];
    const float* bih2 = (const float*)d_in[7];
    const float* bhh2 = (const float*)d_in[8];
    const float* Wih3 = (const float*)d_in[9];
    const float* Whh3 = (const float*)d_in[10];
    const float* bih3 = (const float*)d_in[11];
    const float* bhh3 = (const float*)d_in[12];
    const float* fcW  = (const float*)d_in[13];
    const float* fcb  = (const float*)d_in[14];

    size_t shbytes = (size_t)SH_FLOATS * sizeof(float);
    cudaFuncSetAttribute(lstm3_fused_kernel,
                         cudaFuncAttributeMaxDynamicSharedMemorySize,
                         (int)shbytes);
    lstm3_fused_kernel<<<GRID, NTHREADS, shbytes>>>(
        x, Wih1, Whh1, bih1, bhh1, Wih2, Whh2, bih2, bhh2,
        Wih3, Whh3, bih3, bhh3, fcW, fcb, (float*)d_out);
}

// round 7
// speedup vs baseline: 1.4059x; 1.4059x over previous
#include <cuda_runtime.h>

// 3-layer LSTM (IN=5, H=50) + FC(50->1), B=1024, T=512.
// v6: layer-pipelined warp specialization. At phase ph:
//   L1 group (50 thr, warps 0-1)   computes layer1 @ t = ph
//   L2 group (200 thr, warps 2-8)  computes layer2 @ t = ph-1
//   L3 group (200 thr, warps 9-15) computes layer3 @ t = ph-2
//   spare threads (488-511)        prefetch x(ph+1)
// All v vectors double-buffered on phase parity: reads from p, writes to q
// -> ONE __syncthreads per phase (514 phases) instead of 3 per step.
// L2/L3 use R4's proven 4-way K-split + 7-batch accumulators + pick4
// extraction (no dynamic register indexing anywhere). Cell states in regs.

#define T_STEPS   512
#define IN_DIM    5
#define HID       50
#define NB        7
#define NTHREADS  512
#define GRID      148
#define WSTR      808          // floats per kq block (200 rows * 4 + 8 pad)

// smem offsets (floats)
enum {
    W1_OFF = 0,                 // 14 * 808 = 11312
    W2_OFF = 11312,             // 25 * 808 = 20200
    W3_OFF = 31512,             // 20200
    V1_OFF = 51712,             // 2 bufs * 7 * 60   [x(5),pad,h1(50),pad4]
    V2_OFF = 52552,             // 2 bufs * 7 * 108  [h1(50),h2(50),pad8]
    V3_OFF = 54064,             // 2 bufs * 7 * 108  [h2(50),h3(50),pad8]
    SH_FLOATS = 55576           // 222304 bytes
};
#define V1S 60
#define V2S 108
#define V1B (NB * V1S)          // 420
#define V2B (NB * V2S)          // 756

typedef unsigned long long ull;

__device__ __forceinline__ ull ffma2(ull a, ull b, ull c) {
    ull d;
    asm("fma.rn.f32x2 %0, %1, %2, %3;" : "=l"(d) : "l"(a), "l"(b), "l"(c));
    return d;
}
__device__ __forceinline__ float fast_ex2(float x) {
    float y; asm("ex2.approx.ftz.f32 %0, %1;" : "=f"(y) : "f"(x)); return y;
}
__device__ __forceinline__ float fast_rcp(float x) {
    float y; asm("rcp.approx.ftz.f32 %0, %1;" : "=f"(y) : "f"(x)); return y;
}
__device__ __forceinline__ float sigm(float x) {
    return fast_rcp(1.0f + fast_ex2(-1.4426950408889634f * x));
}
__device__ __forceinline__ float tanh_acc(float x) {
    float r = fast_rcp(1.0f + fast_ex2(-2.8853900817779268f * x));
    return r + r - 1.0f;
}
__device__ __forceinline__ float lohi(ull a) {
    float lo, hi;
    asm("mov.b64 {%0, %1}, %2;" : "=f"(lo), "=f"(hi) : "l"(a));
    return lo + hi;
}
__device__ __forceinline__ float pick4(float a0, float a1, float a2, float a3,
                                       int k) {
    float x = (k & 1) ? a1 : a0;
    float y = (k & 1) ? a3 : a2;
    return (k & 2) ? y : x;
}

// ---- Layer 1: 50 threads, no K-split, full 14 kq iters, 7 batches ----
__device__ __forceinline__ void layer1_phase(float* sh, int p, int q, int j,
                                             const float bz[4], float c1[NB]) {
    ull acc[4][NB];
#pragma unroll
    for (int g = 0; g < 4; g++)
#pragma unroll
        for (int b = 0; b < NB; b++) acc[g][b] = 0ull;

    const float* vb = sh + V1_OFF + p * V1B;
#pragma unroll 7
    for (int i = 0; i < 14; i++) {
        const ulonglong2* wq =
            reinterpret_cast<const ulonglong2*>(sh + W1_OFF + i * WSTR);
        ulonglong2 w0 = wq[j];
        ulonglong2 w1 = wq[j + HID];
        ulonglong2 w2 = wq[j + 2 * HID];
        ulonglong2 w3 = wq[j + 3 * HID];
#pragma unroll
        for (int b = 0; b < NB; b++) {
            ulonglong2 v = *reinterpret_cast<const ulonglong2*>(
                vb + b * V1S + i * 4);
            acc[0][b] = ffma2(w0.x, v.x, acc[0][b]);
            acc[0][b] = ffma2(w0.y, v.y, acc[0][b]);
            acc[1][b] = ffma2(w1.x, v.x, acc[1][b]);
            acc[1][b] = ffma2(w1.y, v.y, acc[1][b]);
            acc[2][b] = ffma2(w2.x, v.x, acc[2][b]);
            acc[2][b] = ffma2(w2.y, v.y, acc[2][b]);
            acc[3][b] = ffma2(w3.x, v.x, acc[3][b]);
            acc[3][b] = ffma2(w3.y, v.y, acc[3][b]);
        }
    }
#pragma unroll
    for (int b = 0; b < NB; b++) {
        float iv = sigm(lohi(acc[0][b]) + bz[0]);
        float fv = sigm(lohi(acc[1][b]) + bz[1]);
        float gv = tanh_acc(lohi(acc[2][b]) + bz[2]);
        float ov = sigm(lohi(acc[3][b]) + bz[3]);
        c1[b] = fv * c1[b] + iv * gv;
        float h = ov * tanh_acc(c1[b]);
        sh[V1_OFF + q * V1B + b * V1S + 6 + j] = h;   // own recurrent input
        sh[V2_OFF + q * V2B + b * V2S + j]     = h;   // layer2 input
    }
}

// ---- Layers 2/3: 200 threads, 4-way K-split over KQ=25, 7 batches ----
// wr1/wr2: float offsets into sh WITHOUT the b*V2S term (added per batch).
template<bool HAS2>
__device__ __forceinline__ void layer_hid_phase(float* sh,
                                                const float* __restrict__ shw,
                                                const float* __restrict__ vrd,
                                                int j, int ks, unsigned mask,
                                                const float bz[4],
                                                float& ca, float& cb,
                                                int wr1, int wr2) {
    ull acc[4][NB];
#pragma unroll
    for (int g = 0; g < 4; g++)
#pragma unroll
        for (int b = 0; b < NB; b++) acc[g][b] = 0ull;

#pragma unroll
    for (int i = 0; i < 6; i++) {
        const int kq0 = 4 * i;   // + ks at runtime
        const ulonglong2* wq = reinterpret_cast<const ulonglong2*>(
            shw + (ks + kq0) * WSTR);
        ulonglong2 w0 = wq[j];
        ulonglong2 w1 = wq[j + HID];
        ulonglong2 w2 = wq[j + 2 * HID];
        ulonglong2 w3 = wq[j + 3 * HID];
#pragma unroll
        for (int b = 0; b < NB; b++) {
            ulonglong2 v = *reinterpret_cast<const ulonglong2*>(
                vrd + b * V2S + (ks + kq0) * 4);
            acc[0][b] = ffma2(w0.x, v.x, acc[0][b]);
            acc[0][b] = ffma2(w0.y, v.y, acc[0][b]);
            acc[1][b] = ffma2(w1.x, v.x, acc[1][b]);
            acc[1][b] = ffma2(w1.y, v.y, acc[1][b]);
            acc[2][b] = ffma2(w2.x, v.x, acc[2][b]);
            acc[2][b] = ffma2(w2.y, v.y, acc[2][b]);
            acc[3][b] = ffma2(w3.x, v.x, acc[3][b]);
            acc[3][b] = ffma2(w3.y, v.y, acc[3][b]);
        }
    }
    if (ks == 0) {   // tail block kq = 24 (ks=0 lanes only)
        const ulonglong2* wq = reinterpret_cast<const ulonglong2*>(
            shw + 24 * WSTR);
        ulonglong2 w0 = wq[j];
        ulonglong2 w1 = wq[j + HID];
        ulonglong2 w2 = wq[j + 2 * HID];
        ulonglong2 w3 = wq[j + 3 * HID];
#pragma unroll
        for (int b = 0; b < NB; b++) {
            ulonglong2 v = *reinterpret_cast<const ulonglong2*>(
                vrd + b * V2S + 24 * 4);
            acc[0][b] = ffma2(w0.x, v.x, acc[0][b]);
            acc[0][b] = ffma2(w0.y, v.y, acc[0][b]);
            acc[1][b] = ffma2(w1.x, v.x, acc[1][b]);
            acc[1][b] = ffma2(w1.y, v.y, acc[1][b]);
            acc[2][b] = ffma2(w2.x, v.x, acc[2][b]);
            acc[2][b] = ffma2(w2.y, v.y, acc[2][b]);
            acc[3][b] = ffma2(w3.x, v.x, acc[3][b]);
            acc[3][b] = ffma2(w3.y, v.y, acc[3][b]);
        }
    }

    float s[4][NB];
#pragma unroll
    for (int g = 0; g < 4; g++)
#pragma unroll
        for (int b = 0; b < NB; b++) {
            float v = lohi(acc[g][b]);
            v += __shfl_xor_sync(mask, v, 1);
            v += __shfl_xor_sync(mask, v, 2);
            s[g][b] = v;
        }

    // this thread updates batches 2*ks and 2*ks+1 (ks==3 -> only b=6)
    float t0[4], t1[4];
#pragma unroll
    for (int g = 0; g < 4; g++) {
        t0[g] = pick4(s[g][0], s[g][2], s[g][4], s[g][6], ks) + bz[g];
        t1[g] = pick4(s[g][1], s[g][3], s[g][5], s[g][5], ks) + bz[g];
    }
    const int b0 = 2 * ks;
    {
        float iv = sigm(t0[0]);
        float fv = sigm(t0[1]);
        float gv = tanh_acc(t0[2]);
        float ov = sigm(t0[3]);
        ca = fv * ca + iv * gv;
        float h = ov * tanh_acc(ca);
        sh[wr1 + b0 * V2S] = h;
        if (HAS2) sh[wr2 + b0 * V2S] = h;
    }
    if (ks < 3) {
        const int b1 = 2 * ks + 1;
        float iv = sigm(t1[0]);
        float fv = sigm(t1[1]);
        float gv = tanh_acc(t1[2]);
        float ov = sigm(t1[3]);
        cb = fv * cb + iv * gv;
        float h = ov * tanh_acc(cb);
        sh[wr1 + b1 * V2S] = h;
        if (HAS2) sh[wr2 + b1 * V2S] = h;
    }
}

__global__ void __launch_bounds__(NTHREADS, 1)
lstm3_pipe_kernel(const float* __restrict__ x,
                  const float* __restrict__ Wih1, const float* __restrict__ Whh1,
                  const float* __restrict__ bih1, const float* __restrict__ bhh1,
                  const float* __restrict__ Wih2, const float* __restrict__ Whh2,
                  const float* __restrict__ bih2, const float* __restrict__ bhh2,
                  const float* __restrict__ Wih3, const float* __restrict__ Whh3,
                  const float* __restrict__ bih3, const float* __restrict__ bhh3,
                  const float* __restrict__ fcW, const float* __restrict__ fcb,
                  float* __restrict__ out) {
    extern __shared__ float sh[];
    const int tid = threadIdx.x;
    const int bid = blockIdx.x;

    int b0, cnt;
    if (bid < 136) { b0 = bid * 7;               cnt = 7; }
    else           { b0 = 952 + (bid - 136) * 6; cnt = 6; }

    // zero v buffers (both parities)
    for (int i = V1_OFF + tid; i < SH_FLOATS; i += NTHREADS) sh[i] = 0.0f;

    // stage weights: [kq][row][k&3], kq-stride WSTR
    for (int idx = tid; idx < 200 * 56; idx += NTHREADS) {
        int g = idx / 56, k = idx - g * 56;
        float v;
        if (k < IN_DIM)       v = Wih1[g * IN_DIM + k];
        else if (k == IN_DIM) v = 0.0f;
        else                  v = Whh1[g * HID + (k - 6)];
        sh[W1_OFF + (k >> 2) * WSTR + g * 4 + (k & 3)] = v;
    }
    for (int idx = tid; idx < 200 * 100; idx += NTHREADS) {
        int g = idx / 100, k = idx - g * 100;
        float v = (k < HID) ? Wih2[g * HID + k] : Whh2[g * HID + (k - HID)];
        sh[W2_OFF + (k >> 2) * WSTR + g * 4 + (k & 3)] = v;
    }
    for (int idx = tid; idx < 200 * 100; idx += NTHREADS) {
        int g = idx / 100, k = idx - g * 100;
        float v = (k < HID) ? Wih3[g * HID + k] : Whh3[g * HID + (k - HID)];
        sh[W3_OFF + (k >> 2) * WSTR + g * 4 + (k & 3)] = v;
    }
    // x(t=0) into v1 buf0
    if (tid < NB * IN_DIM) {
        int b = tid / IN_DIM, d = tid - b * IN_DIM;
        if (b < cnt)
            sh[V1_OFF + b * V1S + d] = x[(size_t)(b0 + b) * T_STEPS * IN_DIM + d];
    }

    // ---- group assignment (warp-aligned) ----
    const bool isL1 = (tid < 50);                      // warps 0-1
    const bool isL2 = (tid >= 64  && tid < 264);       // warps 2-8
    const bool isL3 = (tid >= 288 && tid < 488);       // warps 9-15
    const bool isSp = (tid >= 488 && tid < 488 + 24);  // warp 15 tail

    int j = 0, ks = 0;
    unsigned mask = 0xFFFFFFFFu;
    if (isL1) { j = tid; }
    else if (isL2) { int i2 = tid - 64;  j = i2 >> 2; ks = i2 & 3;
                     mask = (tid < 256) ? 0xFFFFFFFFu : 0x000000FFu; }
    else if (isL3) { int i3 = tid - 288; j = i3 >> 2; ks = i3 & 3;
                     mask = (tid < 480) ? 0xFFFFFFFFu : 0x000000FFu; }

    float bz[4] = {0.f, 0.f, 0.f, 0.f};
    if (isL1) {
#pragma unroll
        for (int g = 0; g < 4; g++)
            bz[g] = bih1[g * HID + j] + bhh1[g * HID + j];
    } else if (isL2) {
#pragma unroll
        for (int g = 0; g < 4; g++)
            bz[g] = bih2[g * HID + j] + bhh2[g * HID + j];
    } else if (isL3) {
#pragma unroll
        for (int g = 0; g < 4; g++)
            bz[g] = bih3[g * HID + j] + bhh3[g * HID + j];
    }

    float c1[NB];
#pragma unroll
    for (int b = 0; b < NB; b++) c1[b] = 0.0f;
    float ca = 0.f, cb = 0.f;    // L2/L3 cell states (batches 2ks, 2ks+1)

    // spare prefetch slots: thread i handles slots i and i+24
    int sp_i = tid - 488;
    __syncthreads();

    for (int ph = 0; ph < T_STEPS + 2; ph++) {
        const int p = ph & 1, q = p ^ 1;

        if (isL1) {
            if (ph < T_STEPS)
                layer1_phase(sh, p, q, j, bz, c1);
        } else if (isL2) {
            if (ph >= 1 && ph <= T_STEPS)
                layer_hid_phase<true>(sh, sh + W2_OFF,
                                      sh + V2_OFF + p * V2B,
                                      j, ks, mask, bz, ca, cb,
                                      V2_OFF + q * V2B + HID + j,
                                      V3_OFF + q * V2B + j);
        } else if (isL3) {
            if (ph >= 2)
                layer_hid_phase<false>(sh, sh + W3_OFF,
                                       sh + V3_OFF + p * V2B,
                                       j, ks, mask, bz, ca, cb,
                                       V3_OFF + q * V2B + HID + j, 0);
        } else if (isSp) {
            if (ph + 1 < T_STEPS) {
                int s0 = sp_i;
                int bb = s0 / IN_DIM, dd = s0 - bb * IN_DIM;
                if (bb < cnt)
                    sh[V1_OFF + q * V1B + bb * V1S + dd] =
                        x[(size_t)(b0 + bb) * T_STEPS * IN_DIM
                          + (ph + 1) * IN_DIM + dd];
                int s1 = sp_i + 24;
                if (s1 < NB * IN_DIM) {
                    int b2 = s1 / IN_DIM, d2 = s1 - b2 * IN_DIM;
                    if (b2 < cnt)
                        sh[V1_OFF + q * V1B + b2 * V1S + d2] =
                            x[(size_t)(b0 + b2) * T_STEPS * IN_DIM
                              + (ph + 1) * IN_DIM + d2];
                }
            }
        }
        __syncthreads();
    }

    // FC: h3(511) written at ph=513 (q=0) -> v3 buf0, offset 50+j
    if (tid < cnt) {
        float a = fcb[0];
#pragma unroll
        for (int jj = 0; jj < HID; jj++)
            a += fcW[jj] * sh[V3_OFF + tid * V2S + HID + jj];
        out[b0 + tid] = a;
    }
}

extern "C" void kernel_launch(void* const* d_in, const int* in_sizes, int n_in,
                              void* d_out, int out_size) {
    const float* x    = (const float*)d_in[0];
    const float* Wih1 = (const float*)d_in[1];
    const float* Whh1 = (const float*)d_in[2];
    const float* bih1 = (const float*)d_in[3];
    const float* bhh1 = (const float*)d_in[4];
    const float* Wih2 = (const float*)d_in[5];
    const float* Whh2 = (const float*)d_in[6];
    const float* bih2 = (const float*)d_in[7];
    const float* bhh2 = (const float*)d_in[8];
    const float* Wih3 = (const float*)d_in[9];
    const float* Whh3 = (const float*)d_in[10];
    const float* bih3 = (const float*)d_in[11];
    const float* bhh3 = (const float*)d_in[12];
    const float* fcW  = (const float*)d_in[13];
    const float* fcb  = (const float*)d_in[14];

    size_t shbytes = (size_t)SH_FLOATS * sizeof(float);
    cudaFuncSetAttribute(lstm3_pipe_kernel,
                         cudaFuncAttributeMaxDynamicSharedMemorySize,
                         (int)shbytes);
    lstm3_pipe_kernel<<<GRID, NTHREADS, shbytes>>>(
        x, Wih1, Whh1, bih1, bhh1, Wih2, Whh2, bih2, bhh2,
        Wih3, Whh3, bih3, bhh3, fcW, fcb, (float*)d_out);
}